// round 4
// baseline (speedup 1.0000x reference)
#include <cuda_runtime.h>
#include <cuda_fp16.h>
#include <cstdint>

// SplineGCN, round 3:
//   counting-sort edges by source node (col) -> L1-local Z gathers,
//   pre-packed 16B per-edge records, 16-warp GEMM blocks.

#define MAXN 50176            // 196 * 256
#define MAXE 1605632
#define KO 2048               // 64 kernels * 32 out
#define BROW_STRIDE 2056      // 2048 + 8 pad (u32)
#define CPITCH 36             // C staging pitch in u32

__device__ __half   g_Z[(size_t)MAXN * KO];   // ~205 MB fp16 scratch
__device__ uint32_t g_Bperm[16 * KO];
__device__ int      g_hist[MAXN];
__device__ int      g_cursor[MAXN];
__device__ int      g_part[256];
__device__ int      g_degi[MAXN];
__device__ uint4    g_rec[MAXE];              // packed sorted edge records

static __device__ __forceinline__ uint32_t h2u(__half2 h) {
    return *reinterpret_cast<uint32_t*>(&h);
}

// ---------------- zero ----------------
__global__ void zero_kernel(float* __restrict__ out, int n) {
    int i = blockIdx.x * blockDim.x + threadIdx.x;
    if (i < n * 32) out[i] = 0.0f;
    if (i < MAXN) { g_hist[i] = 0; g_degi[i] = 0; }
}

// ---------------- histogram (bin counts + degree) ----------------
__global__ void hist_kernel(const int* __restrict__ ei, int E) {
    int e = blockIdx.x * blockDim.x + threadIdx.x;
    if (e >= E) return;
    atomicAdd(&g_hist[ei[E + e]], 1);   // col bins
    atomicAdd(&g_degi[ei[e]], 1);       // row degree
}

// ---------------- two-level exclusive scan over MAXN bins ----------------
__global__ void scan1_kernel() {
    __shared__ int sh[256];
    int t = threadIdx.x, i = blockIdx.x * 256 + t;
    int v = g_hist[i];
    sh[t] = v; __syncthreads();
#pragma unroll
    for (int o = 1; o < 256; o <<= 1) {
        int u = (t >= o) ? sh[t - o] : 0;
        __syncthreads();
        sh[t] += u;
        __syncthreads();
    }
    g_cursor[i] = sh[t] - v;
    if (t == 255) g_part[blockIdx.x] = sh[255];
}
__global__ void scan2_kernel(int nb) {
    __shared__ int sh[256];
    int t = threadIdx.x;
    int v = (t < nb) ? g_part[t] : 0;
    sh[t] = v; __syncthreads();
#pragma unroll
    for (int o = 1; o < 256; o <<= 1) {
        int u = (t >= o) ? sh[t - o] : 0;
        __syncthreads();
        sh[t] += u;
        __syncthreads();
    }
    g_part[t] = sh[t] - v;
}
__global__ void scan3_kernel() {
    int i = blockIdx.x * 256 + threadIdx.x;
    g_cursor[i] += g_part[blockIdx.x];
}

// ---------------- scatter into sorted, packed records ----------------
__global__ void scatter_kernel(const float* __restrict__ pseudo,
                               const int* __restrict__ ei, int E) {
    int e = blockIdx.x * blockDim.x + threadIdx.x;
    if (e >= E) return;
    int row = ei[e];
    int col = ei[E + e];

    float v0 = pseudo[e * 3 + 0] * 3.0f;
    float v1 = pseudo[e * 3 + 1] * 3.0f;
    float v2 = pseudo[e * 3 + 2] * 3.0f;
    int b0 = (int)v0; b0 = b0 > 2 ? 2 : b0;
    int b1 = (int)v1; b1 = b1 > 2 ? 2 : b1;
    int b2 = (int)v2; b2 = b2 > 2 ? 2 : b2;
    float f0 = v0 - (float)b0, f1 = v1 - (float)b1, f2 = v2 - (float)b2;
    int base = b0 + (b1 << 2) + (b2 << 4);

    int q0 = min((int)(f0 * 65536.0f), 65535);
    int q1 = min((int)(f1 * 65536.0f), 65535);
    int q2 = min((int)(f2 * 65536.0f), 65535);

    int pos = atomicAdd(&g_cursor[col], 1);
    g_rec[pos] = make_uint4((uint32_t)row | ((uint32_t)col << 16),
                            (uint32_t)q0 | ((uint32_t)q1 << 16),
                            (uint32_t)q2 | ((uint32_t)base << 16), 0u);
}

// ---------------- weight permute ----------------
__global__ void prep_kernel(const float* __restrict__ w) {
    int i = blockIdx.x * blockDim.x + threadIdx.x;
    if (i >= 16 * KO) return;
    int kk = i >> 11, c = i & 2047;
    int k = c >> 5, o = c & 31;
    float w0 = w[k * 1024 + (2 * kk) * 32 + o];
    float w1 = w[k * 1024 + (2 * kk + 1) * 32 + o];
    g_Bperm[i] = h2u(__floats2half2_rn(w0, w1));
}

static __device__ __forceinline__ uint32_t lda(const float* __restrict__ f, int r, int c, int n) {
    if (r >= n) return 0u;
    float2 v = *reinterpret_cast<const float2*>(f + (size_t)r * 32 + c);
    return h2u(__floats2half2_rn(v.x, v.y));
}

// ---------------- Z = feat @ W (fp16 out), 16 warps / block ----------------
__global__ void __launch_bounds__(512) gemm_kernel(const float* __restrict__ feat, int n) {
    extern __shared__ uint32_t smem[];
    uint32_t* sB = smem;
    const uint4* src = reinterpret_cast<const uint4*>(g_Bperm);
    for (int i = threadIdx.x; i < 16 * KO / 4; i += blockDim.x) {
        int r = i >> 9, c4 = (i & 511) << 2;
        *reinterpret_cast<uint4*>(&sB[r * BROW_STRIDE + c4]) = src[i];
    }
    __syncthreads();

    int warp = threadIdx.x >> 5, lane = threadIdx.x & 31;
    int g = lane >> 2, t4 = lane & 3;
    int n0 = blockIdx.x * 256 + warp * 16;
    if (n0 >= n) return;
    uint32_t* sC = smem + 16 * BROW_STRIDE + warp * (16 * CPITCH);

    int r0 = n0 + g, r1 = r0 + 8;
    uint32_t a[2][4];
#pragma unroll
    for (int ks = 0; ks < 2; ks++) {
        int c0 = ks * 16 + t4 * 2;
        a[ks][0] = lda(feat, r0, c0, n);
        a[ks][1] = lda(feat, r1, c0, n);
        a[ks][2] = lda(feat, r0, c0 + 8, n);
        a[ks][3] = lda(feat, r1, c0 + 8, n);
    }

    for (int oc = 0; oc < KO; oc += 64) {
#pragma unroll
        for (int nb = 0; nb < 8; nb++) {
            int col = oc + nb * 8 + g;
            float c0 = 0.f, c1 = 0.f, c2 = 0.f, c3 = 0.f;
#pragma unroll
            for (int ks = 0; ks < 2; ks++) {
                uint32_t b0 = sB[(ks * 8 + t4) * BROW_STRIDE + col];
                uint32_t b1 = sB[(ks * 8 + t4 + 4) * BROW_STRIDE + col];
                asm volatile(
                    "mma.sync.aligned.m16n8k16.row.col.f32.f16.f16.f32 "
                    "{%0,%1,%2,%3}, {%4,%5,%6,%7}, {%8,%9}, {%0,%1,%2,%3};"
                    : "+f"(c0), "+f"(c1), "+f"(c2), "+f"(c3)
                    : "r"(a[ks][0]), "r"(a[ks][1]), "r"(a[ks][2]), "r"(a[ks][3]),
                      "r"(b0), "r"(b1));
            }
            sC[g * CPITCH + nb * 4 + t4]       = h2u(__floats2half2_rn(c0, c1));
            sC[(g + 8) * CPITCH + nb * 4 + t4] = h2u(__floats2half2_rn(c2, c3));
        }
        __syncwarp();
#pragma unroll
        for (int p = 0; p < 4; p++) {
            int idx = p * 32 + lane;
            int ri = idx >> 3, q = idx & 7;
            int rr = n0 + ri;
            if (rr < n) {
                uint4 v = *reinterpret_cast<const uint4*>(sC + ri * CPITCH + q * 4);
                *reinterpret_cast<uint4*>(g_Z + (size_t)rr * KO + oc + q * 8) = v;
            }
        }
        __syncwarp();
    }
}

// ---------------- sorted edge gather + scatter-add ----------------
__global__ void __launch_bounds__(256) edge_kernel(float* __restrict__ out, int E) {
    int t = blockIdx.x * blockDim.x + threadIdx.x;
    int e = t >> 2;
    if (e >= E) return;
    int l4 = t & 3;

    uint4 r = __ldg(&g_rec[e]);
    int row = r.x & 0xFFFF;
    int col = r.x >> 16;
    const float iq = 1.0f / 65536.0f;
    float f0 = (float)(r.y & 0xFFFF) * iq;
    float f1 = (float)(r.y >> 16) * iq;
    float f2 = (float)(r.z & 0xFFFF) * iq;
    int base = r.z >> 16;

    const __half* zp = g_Z + (size_t)col * KO + l4 * 8;

    float a0 = 0.f, a1 = 0.f, a2 = 0.f, a3 = 0.f, a4 = 0.f, a5 = 0.f, a6 = 0.f, a7 = 0.f;
#pragma unroll
    for (int s = 0; s < 8; s++) {
        float w = ((s & 1) ? f0 : 1.0f - f0) *
                  ((s & 2) ? f1 : 1.0f - f1) *
                  ((s & 4) ? f2 : 1.0f - f2);
        int k = base + (s & 1) + ((s & 2) << 1) + ((s & 4) << 2);
        uint4 u = __ldg(reinterpret_cast<const uint4*>(zp + (k << 5)));
        float2 p0 = __half22float2(*reinterpret_cast<__half2*>(&u.x));
        float2 p1 = __half22float2(*reinterpret_cast<__half2*>(&u.y));
        float2 p2 = __half22float2(*reinterpret_cast<__half2*>(&u.z));
        float2 p3 = __half22float2(*reinterpret_cast<__half2*>(&u.w));
        a0 = fmaf(w, p0.x, a0); a1 = fmaf(w, p0.y, a1);
        a2 = fmaf(w, p1.x, a2); a3 = fmaf(w, p1.y, a3);
        a4 = fmaf(w, p2.x, a4); a5 = fmaf(w, p2.y, a5);
        a6 = fmaf(w, p3.x, a6); a7 = fmaf(w, p3.y, a7);
    }

    float* dst = out + (size_t)row * 32 + l4 * 8;
    asm volatile("red.global.add.v4.f32 [%0], {%1,%2,%3,%4};"
                 :: "l"(dst), "f"(a0), "f"(a1), "f"(a2), "f"(a3) : "memory");
    asm volatile("red.global.add.v4.f32 [%0], {%1,%2,%3,%4};"
                 :: "l"(dst + 4), "f"(a4), "f"(a5), "f"(a6), "f"(a7) : "memory");
}

// ---------------- finalize ----------------
__global__ void final_kernel(float* __restrict__ out, const float* __restrict__ bias, int n) {
    int i = blockIdx.x * blockDim.x + threadIdx.x;
    if (i >= n * 32) return;
    float d = (float)g_degi[i >> 5];
    out[i] = out[i] / fmaxf(d, 1.0f) + bias[i & 31];
}

extern "C" void kernel_launch(void* const* d_in, const int* in_sizes, int n_in,
                              void* d_out, int out_size) {
    const float* feat   = (const float*)d_in[0];
    const float* pseudo = (const float*)d_in[1];
    const float* weight = (const float*)d_in[2];
    const float* bias   = (const float*)d_in[3];
    const int*   ei     = (const int*)d_in[4];
    int n = in_sizes[0] / 32;
    int E = in_sizes[4] / 2;
    float* out = (float*)d_out;

    const int nb_scan = MAXN / 256;  // 196
    const int smem_bytes = (16 * BROW_STRIDE + 16 * 16 * CPITCH) * 4;  // ~164.5 KB
    cudaFuncSetAttribute(gemm_kernel, cudaFuncAttributeMaxDynamicSharedMemorySize, smem_bytes);

    zero_kernel<<<(n * 32 + 255) / 256, 256>>>(out, n);
    hist_kernel<<<(E + 255) / 256, 256>>>(ei, E);
    scan1_kernel<<<nb_scan, 256>>>();
    scan2_kernel<<<1, 256>>>(nb_scan);
    scan3_kernel<<<nb_scan, 256>>>();
    scatter_kernel<<<(E + 255) / 256, 256>>>(pseudo, ei, E);
    prep_kernel<<<(16 * KO + 255) / 256, 256>>>(weight);
    gemm_kernel<<<(n + 255) / 256, 512, smem_bytes>>>(feat, n);
    edge_kernel<<<(E * 4 + 255) / 256, 256>>>(out, E);
    final_kernel<<<(n * 32 + 255) / 256, 256>>>(out, bias, n);
}

// round 5
// speedup vs baseline: 1.0197x; 1.0197x over previous
#include <cuda_runtime.h>
#include <cuda_fp16.h>
#include <cstdint>

// SplineGCN round 5: fully fused smem-resident Z + sorted message stores.
//   - counting sort edges by source (col) -> per-block contiguous edge segments
//   - second cursor by target (row) -> each edge gets a message slot; final pass is a
//     contiguous segmented mean (no atomics anywhere in the hot path)
//   - fused kernel: 48-node Z tile (48 x 2048 fp16) built via mma.sync into smem,
//     then edges gather 8 corners from LDS and store 64B fp16 messages.

#define MAXN 50176            // 196 * 256
#define MAXE 1605632
#define KO 2048               // 64 kernels * 32 out
#define NPB 48                // source nodes per fused block
#define ZS 2056               // smem Z row stride in halfs (4112B; 16B-shift per row)

__device__ uint32_t g_Bperm[16 * KO];   // half2-packed weights
__device__ int      g_hist[MAXN];       // col histogram
__device__ int      g_degi[MAXN];       // row histogram (degree)
__device__ int      g_startc[MAXN];     // col segment starts (immutable)
__device__ int      g_curc[MAXN];       // col scatter cursor
__device__ int      g_curr[MAXN];       // row slot cursor (ends after scatter)
__device__ int      g_part[256];
__device__ uint4    g_rec[MAXE];        // {col, q0|q1, q2|base<<16, msg_slot}
__device__ __half   g_msg[(size_t)MAXE * 32];   // ~103 MB fp16 messages

static __device__ __forceinline__ uint32_t h2u(__half2 h) {
    return *reinterpret_cast<uint32_t*>(&h);
}

// ---------------- zero histograms ----------------
__global__ void zero_kernel() {
    int i = blockIdx.x * blockDim.x + threadIdx.x;
    if (i < MAXN) { g_hist[i] = 0; g_degi[i] = 0; }
}

// ---------------- histograms ----------------
__global__ void hist_kernel(const int* __restrict__ ei, int E) {
    int e = blockIdx.x * blockDim.x + threadIdx.x;
    if (e >= E) return;
    atomicAdd(&g_hist[ei[E + e]], 1);   // source bins
    atomicAdd(&g_degi[ei[e]], 1);       // target degree
}

// ---------------- two-level exclusive scan (MAXN = 196*256) ----------------
__global__ void scan1_kernel(const int* __restrict__ in, int* __restrict__ out) {
    __shared__ int sh[256];
    int t = threadIdx.x, i = blockIdx.x * 256 + t;
    int v = in[i];
    sh[t] = v; __syncthreads();
#pragma unroll
    for (int o = 1; o < 256; o <<= 1) {
        int u = (t >= o) ? sh[t - o] : 0;
        __syncthreads();
        sh[t] += u;
        __syncthreads();
    }
    out[i] = sh[t] - v;
    if (t == 255) g_part[blockIdx.x] = sh[255];
}
__global__ void scan2_kernel(int nb) {
    __shared__ int sh[256];
    int t = threadIdx.x;
    int v = (t < nb) ? g_part[t] : 0;
    sh[t] = v; __syncthreads();
#pragma unroll
    for (int o = 1; o < 256; o <<= 1) {
        int u = (t >= o) ? sh[t - o] : 0;
        __syncthreads();
        sh[t] += u;
        __syncthreads();
    }
    g_part[t] = sh[t] - v;
}
__global__ void scan3_kernel(int* __restrict__ out, int* __restrict__ out2) {
    int i = blockIdx.x * 256 + threadIdx.x;
    int v = out[i] + g_part[blockIdx.x];
    out[i] = v;
    if (out2) out2[i] = v;
}

// ---------------- scatter: build sorted, packed records ----------------
__global__ void scatter_kernel(const float* __restrict__ pseudo,
                               const int* __restrict__ ei, int E) {
    int e = blockIdx.x * blockDim.x + threadIdx.x;
    if (e >= E) return;
    int row = ei[e];
    int col = ei[E + e];

    float v0 = pseudo[e * 3 + 0] * 3.0f;
    float v1 = pseudo[e * 3 + 1] * 3.0f;
    float v2 = pseudo[e * 3 + 2] * 3.0f;
    int b0 = (int)v0; b0 = b0 > 2 ? 2 : b0;
    int b1 = (int)v1; b1 = b1 > 2 ? 2 : b1;
    int b2 = (int)v2; b2 = b2 > 2 ? 2 : b2;
    float f0 = v0 - (float)b0, f1 = v1 - (float)b1, f2 = v2 - (float)b2;
    int base = b0 + (b1 << 2) + (b2 << 4);

    int q0 = min((int)(f0 * 65536.0f), 65535);
    int q1 = min((int)(f1 * 65536.0f), 65535);
    int q2 = min((int)(f2 * 65536.0f), 65535);

    int posc = atomicAdd(&g_curc[col], 1);
    int posr = atomicAdd(&g_curr[row], 1);
    g_rec[posc] = make_uint4((uint32_t)col,
                             (uint32_t)q0 | ((uint32_t)q1 << 16),
                             (uint32_t)q2 | ((uint32_t)base << 16),
                             (uint32_t)posr);
}

// ---------------- weight permute ----------------
__global__ void prep_kernel(const float* __restrict__ w) {
    int i = blockIdx.x * blockDim.x + threadIdx.x;
    if (i >= 16 * KO) return;
    int kk = i >> 11, c = i & 2047;
    int k = c >> 5, o = c & 31;
    float w0 = w[k * 1024 + (2 * kk) * 32 + o];
    float w1 = w[k * 1024 + (2 * kk + 1) * 32 + o];
    g_Bperm[i] = h2u(__floats2half2_rn(w0, w1));
}

static __device__ __forceinline__ uint32_t lda(const float* __restrict__ f, int r, int c, int n) {
    if (r >= n) return 0u;
    float2 v = *reinterpret_cast<const float2*>(f + (size_t)r * 32 + c);
    return h2u(__floats2half2_rn(v.x, v.y));
}

// ---------------- fused: Z tile in smem + edge gather + msg store ----------------
__global__ void __launch_bounds__(512) fused_kernel(const float* __restrict__ feat, int n, int E) {
    extern __shared__ uint32_t sZ32[];          // NPB rows * ZS halfs (u32 view: row stride ZS/2)
    const int tid = threadIdx.x;
    const int warp = tid >> 5, lane = tid & 31;
    const int g = lane >> 2, t4 = lane & 3;
    const int nb0 = blockIdx.x * NPB;

    // ---- phase 1: Z[nb0..nb0+48) = feat @ W, fp16 into smem ----
    uint32_t a[3][2][4];
#pragma unroll
    for (int rg = 0; rg < 3; rg++) {
#pragma unroll
        for (int ks = 0; ks < 2; ks++) {
            int c0 = ks * 16 + t4 * 2;
            int r0 = nb0 + rg * 16 + g;
            a[rg][ks][0] = lda(feat, r0, c0, n);
            a[rg][ks][1] = lda(feat, r0 + 8, c0, n);
            a[rg][ks][2] = lda(feat, r0, c0 + 8, n);
            a[rg][ks][3] = lda(feat, r0 + 8, c0 + 8, n);
        }
    }

    const int colbase = warp * 128;             // each warp owns 128 of 2048 columns
#pragma unroll 4
    for (int nb = 0; nb < 16; nb++) {
        int c = colbase + nb * 8 + g;
        uint32_t b[2][2];
#pragma unroll
        for (int ks = 0; ks < 2; ks++) {
            b[ks][0] = g_Bperm[((ks * 8 + t4) << 11) + c];
            b[ks][1] = g_Bperm[((ks * 8 + t4 + 4) << 11) + c];
        }
#pragma unroll
        for (int rg = 0; rg < 3; rg++) {
            float c0 = 0.f, c1 = 0.f, c2 = 0.f, c3 = 0.f;
#pragma unroll
            for (int ks = 0; ks < 2; ks++) {
                asm volatile(
                    "mma.sync.aligned.m16n8k16.row.col.f32.f16.f16.f32 "
                    "{%0,%1,%2,%3}, {%4,%5,%6,%7}, {%8,%9}, {%0,%1,%2,%3};"
                    : "+f"(c0), "+f"(c1), "+f"(c2), "+f"(c3)
                    : "r"(a[rg][ks][0]), "r"(a[rg][ks][1]), "r"(a[rg][ks][2]), "r"(a[rg][ks][3]),
                      "r"(b[ks][0]), "r"(b[ks][1]));
            }
            int row0 = rg * 16 + g;
            int ch2 = (colbase >> 1) + nb * 4 + t4;   // half2 column index
            sZ32[row0 * (ZS / 2) + ch2]       = h2u(__floats2half2_rn(c0, c1));
            sZ32[(row0 + 8) * (ZS / 2) + ch2] = h2u(__floats2half2_rn(c2, c3));
        }
    }
    __syncthreads();

    // ---- phase 2: edges of these 48 nodes gather from smem, store fp16 msg ----
    const __half* sZ = reinterpret_cast<const __half*>(sZ32);
    int estart = g_startc[nb0];
    int eend   = g_startc[nb0 + NPB];   // nb0+NPB <= 50016 < MAXN
    int l4 = tid & 3;

    for (int i = estart + (tid >> 2); i < eend; i += 128) {
        uint4 r = __ldg(&g_rec[i]);
        int local = (int)r.x - nb0;
        const float iq = 1.0f / 65536.0f;
        float f0 = (float)(r.y & 0xFFFF) * iq;
        float f1 = (float)(r.y >> 16) * iq;
        float f2 = (float)(r.z & 0xFFFF) * iq;
        int base = r.z >> 16;

        const __half* zp = sZ + local * ZS + l4 * 8;

        float a0 = 0.f, a1 = 0.f, a2 = 0.f, a3 = 0.f, a4 = 0.f, a5 = 0.f, a6 = 0.f, a7 = 0.f;
#pragma unroll
        for (int s = 0; s < 8; s++) {
            float w = ((s & 1) ? f0 : 1.0f - f0) *
                      ((s & 2) ? f1 : 1.0f - f1) *
                      ((s & 4) ? f2 : 1.0f - f2);
            int k = base + (s & 1) + ((s & 2) << 1) + ((s & 4) << 2);
            uint4 u = *reinterpret_cast<const uint4*>(zp + (k << 5));
            float2 p0 = __half22float2(*reinterpret_cast<__half2*>(&u.x));
            float2 p1 = __half22float2(*reinterpret_cast<__half2*>(&u.y));
            float2 p2 = __half22float2(*reinterpret_cast<__half2*>(&u.z));
            float2 p3 = __half22float2(*reinterpret_cast<__half2*>(&u.w));
            a0 = fmaf(w, p0.x, a0); a1 = fmaf(w, p0.y, a1);
            a2 = fmaf(w, p1.x, a2); a3 = fmaf(w, p1.y, a3);
            a4 = fmaf(w, p2.x, a4); a5 = fmaf(w, p2.y, a5);
            a6 = fmaf(w, p3.x, a6); a7 = fmaf(w, p3.y, a7);
        }
        uint4 m;
        m.x = h2u(__floats2half2_rn(a0, a1));
        m.y = h2u(__floats2half2_rn(a2, a3));
        m.z = h2u(__floats2half2_rn(a4, a5));
        m.w = h2u(__floats2half2_rn(a6, a7));
        *reinterpret_cast<uint4*>(g_msg + (size_t)r.w * 32 + l4 * 8) = m;
    }
}

// ---------------- final: segmented mean over row-sorted messages ----------------
__global__ void __launch_bounds__(256) final_kernel(float* __restrict__ out,
                                                    const float* __restrict__ bias, int n) {
    int t = blockIdx.x * blockDim.x + threadIdx.x;
    int node = t >> 2;
    if (node >= n) return;
    int l4 = t & 3;

    int deg = g_degi[node];
    int start = g_curr[node] - deg;     // cursor holds segment end after scatter

    float a0 = 0.f, a1 = 0.f, a2 = 0.f, a3 = 0.f, a4 = 0.f, a5 = 0.f, a6 = 0.f, a7 = 0.f;
    const __half* mp = g_msg + (size_t)start * 32 + l4 * 8;
    for (int j = 0; j < deg; j++) {
        uint4 u = __ldg(reinterpret_cast<const uint4*>(mp + (size_t)j * 32));
        float2 p0 = __half22float2(*reinterpret_cast<__half2*>(&u.x));
        float2 p1 = __half22float2(*reinterpret_cast<__half2*>(&u.y));
        float2 p2 = __half22float2(*reinterpret_cast<__half2*>(&u.z));
        float2 p3 = __half22float2(*reinterpret_cast<__half2*>(&u.w));
        a0 += p0.x; a1 += p0.y; a2 += p1.x; a3 += p1.y;
        a4 += p2.x; a5 += p2.y; a6 += p3.x; a7 += p3.y;
    }
    float inv = 1.0f / fmaxf((float)deg, 1.0f);
    const float* bp = bias + l4 * 8;
    float* dst = out + (size_t)node * 32 + l4 * 8;
    float4 o0 = make_float4(a0 * inv + bp[0], a1 * inv + bp[1],
                            a2 * inv + bp[2], a3 * inv + bp[3]);
    float4 o1 = make_float4(a4 * inv + bp[4], a5 * inv + bp[5],
                            a6 * inv + bp[6], a7 * inv + bp[7]);
    *reinterpret_cast<float4*>(dst) = o0;
    *reinterpret_cast<float4*>(dst + 4) = o1;
}

extern "C" void kernel_launch(void* const* d_in, const int* in_sizes, int n_in,
                              void* d_out, int out_size) {
    const float* feat   = (const float*)d_in[0];
    const float* pseudo = (const float*)d_in[1];
    const float* weight = (const float*)d_in[2];
    const float* bias   = (const float*)d_in[3];
    const int*   ei     = (const int*)d_in[4];
    int n = in_sizes[0] / 32;
    int E = in_sizes[4] / 2;
    float* out = (float*)d_out;

    const int nb_scan = MAXN / 256;                     // 196
    const int smem_bytes = NPB * ZS * 2;                // 197376 B
    static int configured = 0;
    if (!configured) {
        cudaFuncSetAttribute(fused_kernel, cudaFuncAttributeMaxDynamicSharedMemorySize, smem_bytes);
        configured = 1;
    }

    int* startc = nullptr; int* curc = nullptr; int* curr = nullptr; int* hist = nullptr; int* degi = nullptr;
    cudaGetSymbolAddress((void**)&startc, g_startc);
    cudaGetSymbolAddress((void**)&curc, g_curc);
    cudaGetSymbolAddress((void**)&curr, g_curr);
    cudaGetSymbolAddress((void**)&hist, g_hist);
    cudaGetSymbolAddress((void**)&degi, g_degi);

    zero_kernel<<<(MAXN + 255) / 256, 256>>>();
    hist_kernel<<<(E + 255) / 256, 256>>>(ei, E);
    // col scan -> startc (immutable) + curc (scatter cursor)
    scan1_kernel<<<nb_scan, 256>>>(hist, startc);
    scan2_kernel<<<1, 256>>>(nb_scan);
    scan3_kernel<<<nb_scan, 256>>>(startc, curc);
    // row scan -> curr (slot cursor)
    scan1_kernel<<<nb_scan, 256>>>(degi, curr);
    scan2_kernel<<<1, 256>>>(nb_scan);
    scan3_kernel<<<nb_scan, 256>>>(curr, nullptr);
    scatter_kernel<<<(E + 255) / 256, 256>>>(pseudo, ei, E);
    prep_kernel<<<(16 * KO + 255) / 256, 256>>>(weight);
    fused_kernel<<<(n + NPB - 1) / NPB, 512, smem_bytes>>>(feat, n, E);
    final_kernel<<<(n * 4 + 255) / 256, 256>>>(out, bias, n);
}

// round 6
// speedup vs baseline: 1.1056x; 1.0842x over previous
#include <cuda_runtime.h>
#include <cuda_fp16.h>
#include <cstdint>

// SplineGCN round 6: 6-kernel pipeline, self-cleaning histograms, 1024-thread fused blocks.
//   K1 histprep : col/row histograms (atomics on zeroed tables) + weight permute
//   K2 scan1    : per-chunk exclusive scan of BOTH histograms (zeroes g_hist after read)
//   K3 scan3    : adds inline-computed partial prefix; writes startc/curc/curr
//   K4 scatter  : packed col-sorted records + row-sorted message slot assignment
//   K5 fused    : 48-node Z tile (fp16, smem) via mma.sync, edge gather from LDS, msg store
//   K6 final    : segmented mean over row-sorted messages + bias (zeroes g_degi after read)

#define MAXN 50176            // 196 * 256
#define MAXE 1605632
#define KO 2048               // 64 kernels * 32 out
#define NPB 48                // source nodes per fused block
#define ZS 2056               // smem Z row stride in halfs (4112B)
#define NCHUNK 196            // MAXN / 256
#define NPART 392             // 2 * NCHUNK

__device__ uint32_t g_Bperm[16 * KO];
__device__ int      g_hist[MAXN];       // col histogram (zeroed by scan1 after read)
__device__ int      g_degi[MAXN];       // row histogram (zeroed by final after read)
__device__ int      g_startc[MAXN];     // col segment starts
__device__ int      g_curc[MAXN];       // col scatter cursor
__device__ int      g_curr[MAXN];       // row slot cursor (holds segment END after scatter)
__device__ int      g_part[NPART];
__device__ uint4    g_rec[MAXE];        // {col, q0|q1, q2|base<<16, msg_slot}
__device__ __half   g_msg[(size_t)MAXE * 32];

static __device__ __forceinline__ uint32_t h2u(__half2 h) {
    return *reinterpret_cast<uint32_t*>(&h);
}

// ---------------- K1: histograms + weight permute ----------------
__global__ void histprep_kernel(const int* __restrict__ ei,
                                const float* __restrict__ w, int E, int HB) {
    if ((int)blockIdx.x < HB) {
        int e = blockIdx.x * 256 + threadIdx.x;
        if (e < E) {
            atomicAdd(&g_hist[ei[E + e]], 1);   // source bins
            atomicAdd(&g_degi[ei[e]], 1);       // target degree
        }
    } else {
        int i = (blockIdx.x - HB) * 256 + threadIdx.x;   // < 32768
        int kk = i >> 11, c = i & 2047;
        int k = c >> 5, o = c & 31;
        float w0 = w[k * 1024 + (2 * kk) * 32 + o];
        float w1 = w[k * 1024 + (2 * kk + 1) * 32 + o];
        g_Bperm[i] = h2u(__floats2half2_rn(w0, w1));
    }
}

// ---------------- K2: per-chunk exclusive scan of both histograms ----------------
__global__ void scan1_kernel() {
    __shared__ int sh[256];
    int b = blockIdx.x, t = threadIdx.x;
    bool isB = b >= NCHUNK;
    int i = (isB ? b - NCHUNK : b) * 256 + t;
    int v = isB ? g_degi[i] : g_hist[i];
    sh[t] = v; __syncthreads();
#pragma unroll
    for (int o = 1; o < 256; o <<= 1) {
        int u = (t >= o) ? sh[t - o] : 0;
        __syncthreads();
        sh[t] += u;
        __syncthreads();
    }
    int ex = sh[t] - v;
    if (isB) {
        g_curr[i] = ex;
    } else {
        g_startc[i] = ex;
        g_hist[i] = 0;          // self-clean for next replay
    }
    if (t == 255) g_part[b] = sh[255];
}

// ---------------- K3: add partial prefix (computed inline) ----------------
__global__ void scan3_kernel() {
    __shared__ int red[256];
    int b = blockIdx.x, t = threadIdx.x;
    bool isB = b >= NCHUNK;
    int lo = isB ? NCHUNK : 0;

    int acc = 0;
    if (t >= lo && t < b) acc += g_part[t];
    int t2 = t + 256;
    if (t2 >= lo && t2 < b && t2 < NPART) acc += g_part[t2];
    red[t] = acc; __syncthreads();
#pragma unroll
    for (int o = 128; o > 0; o >>= 1) {
        if (t < o) red[t] += red[t + o];
        __syncthreads();
    }
    int pp = red[0];

    int i = (isB ? b - NCHUNK : b) * 256 + t;
    if (!isB) {
        int v = g_startc[i] + pp;
        g_startc[i] = v;
        g_curc[i] = v;
    } else {
        g_curr[i] += pp;
    }
}

// ---------------- K4: scatter into sorted, packed records ----------------
__global__ void scatter_kernel(const float* __restrict__ pseudo,
                               const int* __restrict__ ei, int E) {
    int e = blockIdx.x * blockDim.x + threadIdx.x;
    if (e >= E) return;
    int row = ei[e];
    int col = ei[E + e];

    float v0 = pseudo[e * 3 + 0] * 3.0f;
    float v1 = pseudo[e * 3 + 1] * 3.0f;
    float v2 = pseudo[e * 3 + 2] * 3.0f;
    int b0 = (int)v0; b0 = b0 > 2 ? 2 : b0;
    int b1 = (int)v1; b1 = b1 > 2 ? 2 : b1;
    int b2 = (int)v2; b2 = b2 > 2 ? 2 : b2;
    float f0 = v0 - (float)b0, f1 = v1 - (float)b1, f2 = v2 - (float)b2;
    int base = b0 + (b1 << 2) + (b2 << 4);

    int q0 = min((int)(f0 * 65536.0f), 65535);
    int q1 = min((int)(f1 * 65536.0f), 65535);
    int q2 = min((int)(f2 * 65536.0f), 65535);

    int posc = atomicAdd(&g_curc[col], 1);
    int posr = atomicAdd(&g_curr[row], 1);
    g_rec[posc] = make_uint4((uint32_t)col,
                             (uint32_t)q0 | ((uint32_t)q1 << 16),
                             (uint32_t)q2 | ((uint32_t)base << 16),
                             (uint32_t)posr);
}

static __device__ __forceinline__ uint32_t lda(const float* __restrict__ f, int r, int c, int n) {
    if (r >= n) return 0u;
    float2 v = *reinterpret_cast<const float2*>(f + (size_t)r * 32 + c);
    return h2u(__floats2half2_rn(v.x, v.y));
}

// ---------------- K5: fused Z tile + edge gather + msg store (1024 threads) ----------------
__global__ void __launch_bounds__(1024) fused_kernel(const float* __restrict__ feat, int n, int E) {
    extern __shared__ uint32_t sZ32[];          // NPB rows * ZS halfs
    const int tid = threadIdx.x;
    const int warp = tid >> 5, lane = tid & 31;
    const int g = lane >> 2, t4 = lane & 3;
    const int nb0 = blockIdx.x * NPB;

    // ---- phase 1: Z[nb0..nb0+48) = feat @ W, fp16 into smem; warp owns 64 cols ----
    uint32_t a[3][2][4];
#pragma unroll
    for (int rg = 0; rg < 3; rg++) {
#pragma unroll
        for (int ks = 0; ks < 2; ks++) {
            int c0 = ks * 16 + t4 * 2;
            int r0 = nb0 + rg * 16 + g;
            a[rg][ks][0] = lda(feat, r0, c0, n);
            a[rg][ks][1] = lda(feat, r0 + 8, c0, n);
            a[rg][ks][2] = lda(feat, r0, c0 + 8, n);
            a[rg][ks][3] = lda(feat, r0 + 8, c0 + 8, n);
        }
    }

    const int colbase = warp * 64;
#pragma unroll 4
    for (int nb = 0; nb < 8; nb++) {
        int c = colbase + nb * 8 + g;
        uint32_t b[2][2];
#pragma unroll
        for (int ks = 0; ks < 2; ks++) {
            b[ks][0] = g_Bperm[((ks * 8 + t4) << 11) + c];
            b[ks][1] = g_Bperm[((ks * 8 + t4 + 4) << 11) + c];
        }
#pragma unroll
        for (int rg = 0; rg < 3; rg++) {
            float c0 = 0.f, c1 = 0.f, c2 = 0.f, c3 = 0.f;
#pragma unroll
            for (int ks = 0; ks < 2; ks++) {
                asm volatile(
                    "mma.sync.aligned.m16n8k16.row.col.f32.f16.f16.f32 "
                    "{%0,%1,%2,%3}, {%4,%5,%6,%7}, {%8,%9}, {%0,%1,%2,%3};"
                    : "+f"(c0), "+f"(c1), "+f"(c2), "+f"(c3)
                    : "r"(a[rg][ks][0]), "r"(a[rg][ks][1]), "r"(a[rg][ks][2]), "r"(a[rg][ks][3]),
                      "r"(b[ks][0]), "r"(b[ks][1]));
            }
            int row0 = rg * 16 + g;
            int ch2 = (colbase >> 1) + nb * 4 + t4;
            sZ32[row0 * (ZS / 2) + ch2]       = h2u(__floats2half2_rn(c0, c1));
            sZ32[(row0 + 8) * (ZS / 2) + ch2] = h2u(__floats2half2_rn(c2, c3));
        }
    }
    __syncthreads();

    // ---- phase 2: edges of these 48 nodes gather from smem, store fp16 msg ----
    const __half* sZ = reinterpret_cast<const __half*>(sZ32);
    int estart = g_startc[nb0];
    int eend   = g_startc[nb0 + NPB];   // nb0+NPB <= 50016 < MAXN
    int l4 = tid & 3;

    for (int i = estart + (tid >> 2); i < eend; i += 256) {
        uint4 r = __ldg(&g_rec[i]);
        int local = (int)r.x - nb0;
        const float iq = 1.0f / 65536.0f;
        float f0 = (float)(r.y & 0xFFFF) * iq;
        float f1 = (float)(r.y >> 16) * iq;
        float f2 = (float)(r.z & 0xFFFF) * iq;
        int base = r.z >> 16;

        const __half* zp = sZ + local * ZS + l4 * 8;

        float a0 = 0.f, a1 = 0.f, a2 = 0.f, a3 = 0.f, a4 = 0.f, a5 = 0.f, a6 = 0.f, a7 = 0.f;
#pragma unroll
        for (int s = 0; s < 8; s++) {
            float w = ((s & 1) ? f0 : 1.0f - f0) *
                      ((s & 2) ? f1 : 1.0f - f1) *
                      ((s & 4) ? f2 : 1.0f - f2);
            int k = base + (s & 1) + ((s & 2) << 1) + ((s & 4) << 2);
            uint4 u = *reinterpret_cast<const uint4*>(zp + (k << 5));
            float2 p0 = __half22float2(*reinterpret_cast<__half2*>(&u.x));
            float2 p1 = __half22float2(*reinterpret_cast<__half2*>(&u.y));
            float2 p2 = __half22float2(*reinterpret_cast<__half2*>(&u.z));
            float2 p3 = __half22float2(*reinterpret_cast<__half2*>(&u.w));
            a0 = fmaf(w, p0.x, a0); a1 = fmaf(w, p0.y, a1);
            a2 = fmaf(w, p1.x, a2); a3 = fmaf(w, p1.y, a3);
            a4 = fmaf(w, p2.x, a4); a5 = fmaf(w, p2.y, a5);
            a6 = fmaf(w, p3.x, a6); a7 = fmaf(w, p3.y, a7);
        }
        uint4 m;
        m.x = h2u(__floats2half2_rn(a0, a1));
        m.y = h2u(__floats2half2_rn(a2, a3));
        m.z = h2u(__floats2half2_rn(a4, a5));
        m.w = h2u(__floats2half2_rn(a6, a7));
        *reinterpret_cast<uint4*>(g_msg + (size_t)r.w * 32 + l4 * 8) = m;
    }
}

// ---------------- K6: segmented mean + bias (self-cleans g_degi) ----------------
__global__ void __launch_bounds__(256) final_kernel(float* __restrict__ out,
                                                    const float* __restrict__ bias, int n) {
    int t = blockIdx.x * blockDim.x + threadIdx.x;
    int node = t >> 2;
    if (node >= n) return;
    int l4 = t & 3;

    int deg = g_degi[node];
    int start = g_curr[node] - deg;     // cursor holds segment end after scatter

    float a0 = 0.f, a1 = 0.f, a2 = 0.f, a3 = 0.f, a4 = 0.f, a5 = 0.f, a6 = 0.f, a7 = 0.f;
    const __half* mp = g_msg + (size_t)start * 32 + l4 * 8;
#pragma unroll 2
    for (int j = 0; j < deg; j++) {
        uint4 u = __ldg(reinterpret_cast<const uint4*>(mp + (size_t)j * 32));
        float2 p0 = __half22float2(*reinterpret_cast<__half2*>(&u.x));
        float2 p1 = __half22float2(*reinterpret_cast<__half2*>(&u.y));
        float2 p2 = __half22float2(*reinterpret_cast<__half2*>(&u.z));
        float2 p3 = __half22float2(*reinterpret_cast<__half2*>(&u.w));
        a0 += p0.x; a1 += p0.y; a2 += p1.x; a3 += p1.y;
        a4 += p2.x; a5 += p2.y; a6 += p3.x; a7 += p3.y;
    }
    float inv = 1.0f / fmaxf((float)deg, 1.0f);
    const float* bp = bias + l4 * 8;
    float* dst = out + (size_t)node * 32 + l4 * 8;
    float4 o0 = make_float4(a0 * inv + bp[0], a1 * inv + bp[1],
                            a2 * inv + bp[2], a3 * inv + bp[3]);
    float4 o1 = make_float4(a4 * inv + bp[4], a5 * inv + bp[5],
                            a6 * inv + bp[6], a7 * inv + bp[7]);
    *reinterpret_cast<float4*>(dst) = o0;
    *reinterpret_cast<float4*>(dst + 4) = o1;

    if (l4 == 0) g_degi[node] = 0;      // self-clean for next replay
}

extern "C" void kernel_launch(void* const* d_in, const int* in_sizes, int n_in,
                              void* d_out, int out_size) {
    const float* feat   = (const float*)d_in[0];
    const float* pseudo = (const float*)d_in[1];
    const float* weight = (const float*)d_in[2];
    const float* bias   = (const float*)d_in[3];
    const int*   ei     = (const int*)d_in[4];
    int n = in_sizes[0] / 32;
    int E = in_sizes[4] / 2;
    float* out = (float*)d_out;

    const int smem_bytes = NPB * ZS * 2;                // 197376 B
    static int configured = 0;
    if (!configured) {
        cudaFuncSetAttribute(fused_kernel, cudaFuncAttributeMaxDynamicSharedMemorySize, smem_bytes);
        configured = 1;
    }

    int HB = (E + 255) / 256;
    histprep_kernel<<<HB + 128, 256>>>(ei, weight, E, HB);
    scan1_kernel<<<NPART, 256>>>();
    scan3_kernel<<<NPART, 256>>>();
    scatter_kernel<<<(E + 255) / 256, 256>>>(pseudo, ei, E);
    fused_kernel<<<(n + NPB - 1) / NPB, 1024, smem_bytes>>>(feat, n, E);
    final_kernel<<<(n * 4 + 255) / 256, 256>>>(out, bias, n);
}